// round 7
// baseline (speedup 1.0000x reference)
#include <cuda_runtime.h>

// RoiPooling: torchvision roi_pool (max), OUT=7x7, SCALE=0.125
// input:  (4, 256, 100, 152) fp32 NCHW
// boxes:  (K, 5) fp32  [batch_idx, x1, y1, x2, y2] image coords
// output: (K, 256, 7, 7) fp32
//
// SEMANTIC (verified R4): XLA rewrites (x / 7.0f) -> x * (1/7.0f); bin sizes
// MUST be computed via __fmul_rn(x, 1.0f/7.0f) to bit-match the reference.
//
// Pipeline:
//  1) transpose NCHW -> NHWC scratch (channels contiguous)
//  2) prep: per-(roi,bin) packed bounds (verified since R6)
//  3) main: warp-task = (bin, 32-channel group); lane = channel ->
//     uniform loop bounds per warp, every load = one 128B line.
//     Outputs staged in smem, written coalesced.

static constexpr int N_   = 4;
static constexpr int C_   = 256;
static constexpr int H_   = 100;
static constexpr int W_   = 152;
static constexpr int HW_  = H_ * W_;
static constexpr int KMAX = 8192;

__device__ float        g_xT[N_ * HW_ * C_];   // NHWC scratch (62.3 MB)
__device__ unsigned int g_bounds[KMAX * 49];   // hs|he<<8|ws<<16|we<<24
__device__ int          g_baseT[KMAX];         // b * HW_ * C_

// ---------------- 1) NCHW -> NHWC transpose (tiled) ----------------
// View per batch as (C_, HW_) -> (HW_, C_). HW_ = 475*32, C_ = 8*32.
__global__ __launch_bounds__(256)
void transpose_nchw_nhwc(const float* __restrict__ x)
{
    __shared__ float tile[32][33];
    const int b   = blockIdx.z;
    const int c0  = blockIdx.y * 32;
    const int hw0 = blockIdx.x * 32;
    const int tx  = threadIdx.x & 31;
    const int ty4 = threadIdx.x >> 5;          // 0..7, each covers 4 rows

    const float* src = x + ((size_t)b * C_) * HW_;
    float*       dst = g_xT + (size_t)b * HW_ * C_;

    #pragma unroll
    for (int i = 0; i < 4; ++i) {
        const int c = c0 + ty4 * 4 + i;
        tile[ty4 * 4 + i][tx] = src[(size_t)c * HW_ + hw0 + tx];
    }
    __syncthreads();
    #pragma unroll
    for (int i = 0; i < 4; ++i) {
        const int hw = hw0 + ty4 * 4 + i;
        dst[(size_t)hw * C_ + c0 + tx] = tile[tx][ty4 * 4 + i];
    }
}

// ---------------- 2) per-(roi,bin) bounds prep ----------------
__global__ __launch_bounds__(256)
void roi_prep(const float* __restrict__ boxes, int kb_total)
{
    const int i = blockIdx.x * blockDim.x + threadIdx.x;
    if (i >= kb_total) return;
    const int bin = i % 49;
    const int k   = i / 49;
    const int pw  = bin % 7;
    const int ph  = bin / 7;

    const float* bx = boxes + (size_t)k * 5;
    const int b  = (int)bx[0];
    const int x1 = __float2int_rn(__fmul_rn(bx[1], 0.125f));
    const int y1 = __float2int_rn(__fmul_rn(bx[2], 0.125f));
    const int x2 = __float2int_rn(__fmul_rn(bx[3], 0.125f));
    const int y2 = __float2int_rn(__fmul_rn(bx[4], 0.125f));
    const int roi_w = max(x2 - x1 + 1, 1);
    const int roi_h = max(y2 - y1 + 1, 1);
    const float RCP7 = 1.0f / 7.0f;            // XLA reciprocal rewrite
    const float bin_h = __fmul_rn((float)roi_h, RCP7);
    const float bin_w = __fmul_rn((float)roi_w, RCP7);

    const int hs = min(max((int)floorf(__fmul_rn((float)ph,       bin_h)) + y1, 0), H_);
    const int he = min(max((int)ceilf (__fmul_rn((float)(ph + 1), bin_h)) + y1, 0), H_);
    const int ws = min(max((int)floorf(__fmul_rn((float)pw,       bin_w)) + x1, 0), W_);
    const int we = min(max((int)ceilf (__fmul_rn((float)(pw + 1), bin_w)) + x1, 0), W_);

    g_bounds[i] = (unsigned)hs | ((unsigned)he << 8)
                | ((unsigned)ws << 16) | ((unsigned)we << 24);
    if (bin == 0) g_baseT[k] = b * HW_ * C_;
}

// ---------------- 3) main gather: warp = (bin, cgroup), lane = channel ----
// CTA: one (roi, 128-channel half). 8 warps x 24.5 tasks of (bin, cgroup).
static constexpr int CPAD = 129;               // smem row pad (129 % 32 = 1)

__global__ __launch_bounds__(256)
void roi_pool_nhwc(float* __restrict__ out)
{
    __shared__ float sres[49 * CPAD];          // 24.7 KB

    const int k    = blockIdx.x >> 1;
    const int half = blockIdx.x & 1;
    const int c0   = half * 128;
    const int wid  = threadIdx.x >> 5;
    const int lane = threadIdx.x & 31;

    const float* src = g_xT + g_baseT[k];
    const unsigned int* bnd = g_bounds + k * 49;

    const float NEG_INF = __int_as_float(0xff800000);

    // 49 bins x 4 channel-groups = 196 warp-tasks
    for (int t = wid; t < 196; t += 8) {
        const int bin    = t >> 2;
        const int cgroup = t & 3;
        const int cloc   = cgroup * 32 + lane;     // 0..127
        const int c      = c0 + cloc;

        const unsigned w32 = bnd[bin];
        const int hs =  w32        & 0xff;
        const int he = (w32 >> 8)  & 0xff;
        const int ws = (w32 >> 16) & 0xff;
        const int we = (w32 >> 24) & 0xff;

        float m = NEG_INF;
        for (int r = hs; r < he; ++r) {
            const float* row = src + ((size_t)r * W_) * C_ + c;
            for (int cc = ws; cc < we; ++cc)
                m = fmaxf(m, __ldg(row + (size_t)cc * C_));  // one 128B line
        }
        const bool empty = (he <= hs) || (we <= ws);
        sres[bin * CPAD + cloc] = empty ? 0.0f : m;
    }
    __syncthreads();

    // coalesced write: out[k*12544 + (c0+cloc)*49 + bin]
    float* dst = out + (size_t)k * (C_ * 49) + (size_t)c0 * 49;
    for (int i = threadIdx.x; i < 128 * 49; i += 256) {
        const int cloc = i / 49;
        const int bin  = i - cloc * 49;
        dst[i] = sres[bin * CPAD + cloc];
    }
}

extern "C" void kernel_launch(void* const* d_in, const int* in_sizes, int n_in,
                              void* d_out, int out_size) {
    const float* x     = (const float*)d_in[0];
    const float* boxes = (const float*)d_in[1];
    float*       out   = (float*)d_out;
    const int K = in_sizes[1] / 5;               // boxes is (K, 5)

    dim3 tg(HW_ / 32, C_ / 32, N_);              // 475 x 8 x 4
    transpose_nchw_nhwc<<<tg, 256>>>(x);

    const int kb_total = K * 49;
    roi_prep<<<(kb_total + 255) / 256, 256>>>(boxes, kb_total);

    roi_pool_nhwc<<<K * 2, 256>>>(out);
}

// round 8
// speedup vs baseline: 2.1308x; 2.1308x over previous
#include <cuda_runtime.h>

// RoiPooling: torchvision roi_pool (max), OUT=7x7, SCALE=0.125
// input:  (4, 256, 100, 152) fp32 NCHW
// boxes:  (K, 5) fp32  [batch_idx, x1, y1, x2, y2] image coords
// output: (K, 256, 7, 7) fp32
//
// SEMANTIC (verified R4): XLA rewrites (x / 7.0f) -> x * (1/7.0f); bin sizes
// MUST be computed via __fmul_rn(x, 1.0f/7.0f) to bit-match the reference.
//
// Pipeline:
//  1) transpose NCHW -> NHWC scratch (verified R7, 22us)
//  2) prep: per-(roi,bin) packed bounds (verified R6)
//  3) main: warp-task = one bin over 128 channels via float4 loads
//     (one LDG.128 per warp covers 128 channels -> 4x fewer instructions
//      than R7). smem-staged coalesced writeout.

static constexpr int N_   = 4;
static constexpr int C_   = 256;
static constexpr int H_   = 100;
static constexpr int W_   = 152;
static constexpr int HW_  = H_ * W_;
static constexpr int C4_  = C_ / 4;            // float4 per cell = 64
static constexpr int KMAX = 8192;

__device__ float        g_xT[N_ * HW_ * C_];   // NHWC scratch (62.3 MB)
__device__ unsigned int g_bounds[KMAX * 49];   // hs|he<<8|ws<<16|we<<24
__device__ int          g_baseT[KMAX];         // b * HW_ * C_

// ---------------- 1) NCHW -> NHWC transpose (tiled) ----------------
__global__ __launch_bounds__(256)
void transpose_nchw_nhwc(const float* __restrict__ x)
{
    __shared__ float tile[32][33];
    const int b   = blockIdx.z;
    const int c0  = blockIdx.y * 32;
    const int hw0 = blockIdx.x * 32;
    const int tx  = threadIdx.x & 31;
    const int ty4 = threadIdx.x >> 5;

    const float* src = x + ((size_t)b * C_) * HW_;
    float*       dst = g_xT + (size_t)b * HW_ * C_;

    #pragma unroll
    for (int i = 0; i < 4; ++i) {
        const int c = c0 + ty4 * 4 + i;
        tile[ty4 * 4 + i][tx] = src[(size_t)c * HW_ + hw0 + tx];
    }
    __syncthreads();
    #pragma unroll
    for (int i = 0; i < 4; ++i) {
        const int hw = hw0 + ty4 * 4 + i;
        dst[(size_t)hw * C_ + c0 + tx] = tile[tx][ty4 * 4 + i];
    }
}

// ---------------- 2) per-(roi,bin) bounds prep ----------------
__global__ __launch_bounds__(256)
void roi_prep(const float* __restrict__ boxes, int kb_total)
{
    const int i = blockIdx.x * blockDim.x + threadIdx.x;
    if (i >= kb_total) return;
    const int bin = i % 49;
    const int k   = i / 49;
    const int pw  = bin % 7;
    const int ph  = bin / 7;

    const float* bx = boxes + (size_t)k * 5;
    const int b  = (int)bx[0];
    const int x1 = __float2int_rn(__fmul_rn(bx[1], 0.125f));
    const int y1 = __float2int_rn(__fmul_rn(bx[2], 0.125f));
    const int x2 = __float2int_rn(__fmul_rn(bx[3], 0.125f));
    const int y2 = __float2int_rn(__fmul_rn(bx[4], 0.125f));
    const int roi_w = max(x2 - x1 + 1, 1);
    const int roi_h = max(y2 - y1 + 1, 1);
    const float RCP7 = 1.0f / 7.0f;            // XLA reciprocal rewrite
    const float bin_h = __fmul_rn((float)roi_h, RCP7);
    const float bin_w = __fmul_rn((float)roi_w, RCP7);

    const int hs = min(max((int)floorf(__fmul_rn((float)ph,       bin_h)) + y1, 0), H_);
    const int he = min(max((int)ceilf (__fmul_rn((float)(ph + 1), bin_h)) + y1, 0), H_);
    const int ws = min(max((int)floorf(__fmul_rn((float)pw,       bin_w)) + x1, 0), W_);
    const int we = min(max((int)ceilf (__fmul_rn((float)(pw + 1), bin_w)) + x1, 0), W_);

    g_bounds[i] = (unsigned)hs | ((unsigned)he << 8)
                | ((unsigned)ws << 16) | ((unsigned)we << 24);
    if (bin == 0) g_baseT[k] = b * HW_ * C_;
}

// ---------------- 3) main gather: warp = bin, lane = 4 channels ----------
static constexpr int SPITCH = 33;              // float4 per bin row (pad)

__global__ __launch_bounds__(256)
void roi_pool_nhwc4(float* __restrict__ out)
{
    __shared__ float4 sres[49 * SPITCH];       // 25.9 KB

    const int k    = blockIdx.x >> 1;
    const int half = blockIdx.x & 1;
    const int c0q  = half * 32;                // float4 offset of channel half
    const int wid  = threadIdx.x >> 5;
    const int lane = threadIdx.x & 31;

    const float4* srcq = (const float4*)g_xT;
    const int baseq = (g_baseT[k] >> 2) + c0q + lane;   // int math only
    const unsigned int* bnd = g_bounds + k * 49;

    const float NI = __int_as_float(0xff800000);

    for (int bin = wid; bin < 49; bin += 8) {
        const unsigned w32 = bnd[bin];
        const int hs =  w32        & 0xff;
        const int he = (w32 >> 8)  & 0xff;
        const int ws = (w32 >> 16) & 0xff;
        const int we = (w32 >> 24) & 0xff;

        float4 m = make_float4(NI, NI, NI, NI);
        for (int r = hs; r < he; ++r) {
            const int rowq = baseq + r * (W_ * C4_);
            int cc = ws;
            for (; cc + 1 < we; cc += 2) {        // unroll-2: 2 indep loads
                const float4 a = srcq[rowq + cc * C4_];
                const float4 b = srcq[rowq + (cc + 1) * C4_];
                m.x = fmaxf(m.x, fmaxf(a.x, b.x));
                m.y = fmaxf(m.y, fmaxf(a.y, b.y));
                m.z = fmaxf(m.z, fmaxf(a.z, b.z));
                m.w = fmaxf(m.w, fmaxf(a.w, b.w));
            }
            if (cc < we) {
                const float4 a = srcq[rowq + cc * C4_];
                m.x = fmaxf(m.x, a.x);
                m.y = fmaxf(m.y, a.y);
                m.z = fmaxf(m.z, a.z);
                m.w = fmaxf(m.w, a.w);
            }
        }
        if ((he <= hs) || (we <= ws))
            m = make_float4(0.f, 0.f, 0.f, 0.f);
        sres[bin * SPITCH + lane] = m;
    }
    __syncthreads();

    // coalesced write: out[k*12544 + (c0 + cloc)*49 + bin]
    const float* s = (const float*)sres;       // bin row = 132 floats
    float* dst = out + (size_t)k * (C_ * 49) + (size_t)(half * 128) * 49;
    for (int i = threadIdx.x; i < 128 * 49; i += 256) {
        const int cloc = i / 49;
        const int bin  = i - cloc * 49;
        dst[i] = s[bin * (SPITCH * 4) + cloc];
    }
}

extern "C" void kernel_launch(void* const* d_in, const int* in_sizes, int n_in,
                              void* d_out, int out_size) {
    const float* x     = (const float*)d_in[0];
    const float* boxes = (const float*)d_in[1];
    float*       out   = (float*)d_out;
    const int K = in_sizes[1] / 5;               // boxes is (K, 5)

    dim3 tg(HW_ / 32, C_ / 32, N_);              // 475 x 8 x 4
    transpose_nchw_nhwc<<<tg, 256>>>(x);

    const int kb_total = K * 49;
    roi_prep<<<(kb_total + 255) / 256, 256>>>(boxes, kb_total);

    roi_pool_nhwc4<<<K * 2, 256>>>(out);
}

// round 9
// speedup vs baseline: 2.2157x; 1.0398x over previous
#include <cuda_runtime.h>

// RoiPooling: torchvision roi_pool (max), OUT=7x7, SCALE=0.125
// input:  (4, 256, 100, 152) fp32 NCHW
// boxes:  (K, 5) fp32  [batch_idx, x1, y1, x2, y2] image coords
// output: (K, 256, 7, 7) fp32
//
// SEMANTIC (verified R4): XLA rewrites (x / 7.0f) -> x * (1/7.0f); bin sizes
// MUST be computed via __fmul_rn(x, 1.0f/7.0f) to bit-match the reference.
//
// Pipeline:
//  1) transpose NCHW -> NHWC scratch, 5 hw-tiles per CTA (MLP=20)
//  2) prep: per-(roi,bin) packed bounds (verified R6)
//  3) main: CTA=(roi, channel-half), 7 warps, warp = bin (exactly 7 bins
//     each), lane = 4 channels (float4). 2x2 unrolled cell loop.

static constexpr int N_   = 4;
static constexpr int C_   = 256;
static constexpr int H_   = 100;
static constexpr int W_   = 152;
static constexpr int HW_  = H_ * W_;
static constexpr int C4_  = C_ / 4;            // float4 per cell = 64
static constexpr int KMAX = 8192;

__device__ float        g_xT[N_ * HW_ * C_];   // NHWC scratch (62.3 MB)
__device__ unsigned int g_bounds[KMAX * 49];   // hs|he<<8|ws<<16|we<<24
__device__ int          g_baseT[KMAX];         // b * HW_ * C_

// ---------------- 1) NCHW -> NHWC transpose: 5 tiles per CTA ----------------
__global__ __launch_bounds__(256)
void transpose_nchw_nhwc(const float* __restrict__ x)
{
    __shared__ float tile[5][32][33];          // 21.1 KB
    const int b   = blockIdx.z;
    const int c0  = blockIdx.y * 32;
    const int hw0 = blockIdx.x * 160;          // 5 x 32 hw cells
    const int tx  = threadIdx.x & 31;
    const int ty4 = threadIdx.x >> 5;          // 0..7

    const float* src = x + ((size_t)b * C_) * HW_;
    float*       dst = g_xT + (size_t)b * HW_ * C_;

    #pragma unroll
    for (int j = 0; j < 5; ++j)
        #pragma unroll
        for (int i = 0; i < 4; ++i) {
            const int c = c0 + ty4 * 4 + i;
            tile[j][ty4 * 4 + i][tx] = src[(size_t)c * HW_ + hw0 + j * 32 + tx];
        }
    __syncthreads();
    #pragma unroll
    for (int j = 0; j < 5; ++j)
        #pragma unroll
        for (int i = 0; i < 4; ++i) {
            const int hw = hw0 + j * 32 + ty4 * 4 + i;
            dst[(size_t)hw * C_ + c0 + tx] = tile[j][tx][ty4 * 4 + i];
        }
}

// ---------------- 2) per-(roi,bin) bounds prep ----------------
__global__ __launch_bounds__(256)
void roi_prep(const float* __restrict__ boxes, int kb_total)
{
    const int i = blockIdx.x * blockDim.x + threadIdx.x;
    if (i >= kb_total) return;
    const int bin = i % 49;
    const int k   = i / 49;
    const int pw  = bin % 7;
    const int ph  = bin / 7;

    const float* bx = boxes + (size_t)k * 5;
    const int b  = (int)bx[0];
    const int x1 = __float2int_rn(__fmul_rn(bx[1], 0.125f));
    const int y1 = __float2int_rn(__fmul_rn(bx[2], 0.125f));
    const int x2 = __float2int_rn(__fmul_rn(bx[3], 0.125f));
    const int y2 = __float2int_rn(__fmul_rn(bx[4], 0.125f));
    const int roi_w = max(x2 - x1 + 1, 1);
    const int roi_h = max(y2 - y1 + 1, 1);
    const float RCP7 = 1.0f / 7.0f;            // XLA reciprocal rewrite
    const float bin_h = __fmul_rn((float)roi_h, RCP7);
    const float bin_w = __fmul_rn((float)roi_w, RCP7);

    const int hs = min(max((int)floorf(__fmul_rn((float)ph,       bin_h)) + y1, 0), H_);
    const int he = min(max((int)ceilf (__fmul_rn((float)(ph + 1), bin_h)) + y1, 0), H_);
    const int ws = min(max((int)floorf(__fmul_rn((float)pw,       bin_w)) + x1, 0), W_);
    const int we = min(max((int)ceilf (__fmul_rn((float)(pw + 1), bin_w)) + x1, 0), W_);

    g_bounds[i] = (unsigned)hs | ((unsigned)he << 8)
                | ((unsigned)ws << 16) | ((unsigned)we << 24);
    if (bin == 0) g_baseT[k] = b * HW_ * C_;
}

// ---------------- 3) main gather: 7 warps, warp = bin, lane = 4 channels ---
static constexpr int SPITCH = 33;              // float4 per bin row (pad)

__device__ __forceinline__ float4 f4max(float4 a, const float4 b) {
    a.x = fmaxf(a.x, b.x); a.y = fmaxf(a.y, b.y);
    a.z = fmaxf(a.z, b.z); a.w = fmaxf(a.w, b.w);
    return a;
}

__global__ __launch_bounds__(224)
void roi_pool_nhwc4(float* __restrict__ out)
{
    __shared__ float4 sres[49 * SPITCH];       // 25.9 KB

    const int k    = blockIdx.x >> 1;
    const int half = blockIdx.x & 1;
    const int c0q  = half * 32;                // float4 offset of channel half
    const int wid  = threadIdx.x >> 5;         // 0..6
    const int lane = threadIdx.x & 31;

    const float4* srcq = (const float4*)g_xT;
    const int baseq = (g_baseT[k] >> 2) + c0q + lane;   // int math only
    const unsigned int* bnd = g_bounds + k * 49;

    const float NI = __int_as_float(0xff800000);

    #pragma unroll
    for (int t = 0; t < 7; ++t) {              // exactly 7 bins per warp
        const int bin = wid * 7 + t;
        const unsigned w32 = bnd[bin];
        const int hs =  w32        & 0xff;
        const int he = (w32 >> 8)  & 0xff;
        const int ws = (w32 >> 16) & 0xff;
        const int we = (w32 >> 24) & 0xff;

        float4 m = make_float4(NI, NI, NI, NI);
        int r = hs;
        for (; r + 1 < he; r += 2) {           // 2 rows per iter
            const int r0 = baseq + r * (W_ * C4_);
            const int r1 = r0 + (W_ * C4_);
            int cc = ws;
            for (; cc + 1 < we; cc += 2) {     // 4 independent LDG.128
                m = f4max(m, srcq[r0 + cc * C4_]);
                m = f4max(m, srcq[r0 + (cc + 1) * C4_]);
                m = f4max(m, srcq[r1 + cc * C4_]);
                m = f4max(m, srcq[r1 + (cc + 1) * C4_]);
            }
            if (cc < we) {
                m = f4max(m, srcq[r0 + cc * C4_]);
                m = f4max(m, srcq[r1 + cc * C4_]);
            }
        }
        if (r < he) {                          // tail row
            const int r0 = baseq + r * (W_ * C4_);
            int cc = ws;
            for (; cc + 1 < we; cc += 2) {
                m = f4max(m, srcq[r0 + cc * C4_]);
                m = f4max(m, srcq[r0 + (cc + 1) * C4_]);
            }
            if (cc < we)
                m = f4max(m, srcq[r0 + cc * C4_]);
        }
        if ((he <= hs) || (we <= ws))
            m = make_float4(0.f, 0.f, 0.f, 0.f);
        sres[bin * SPITCH + lane] = m;
    }
    __syncthreads();

    // coalesced write: out[k*12544 + (c0 + cloc)*49 + bin]
    const float* s = (const float*)sres;       // bin row = 132 floats
    float* dst = out + (size_t)k * (C_ * 49) + (size_t)(half * 128) * 49;
    for (int i = threadIdx.x; i < 128 * 49; i += 224) {   // 28 exact iters
        const int cloc = i / 49;
        const int bin  = i - cloc * 49;
        dst[i] = s[bin * (SPITCH * 4) + cloc];
    }
}

extern "C" void kernel_launch(void* const* d_in, const int* in_sizes, int n_in,
                              void* d_out, int out_size) {
    const float* x     = (const float*)d_in[0];
    const float* boxes = (const float*)d_in[1];
    float*       out   = (float*)d_out;
    const int K = in_sizes[1] / 5;               // boxes is (K, 5)

    dim3 tg(HW_ / 160, C_ / 32, N_);             // 95 x 8 x 4
    transpose_nchw_nhwc<<<tg, 256>>>(x);

    const int kb_total = K * 49;
    roi_prep<<<(kb_total + 255) / 256, 256>>>(boxes, kb_total);

    roi_pool_nhwc4<<<K * 2, 224>>>(out);
}